// round 1
// baseline (speedup 1.0000x reference)
#include <cuda_runtime.h>
#include <cstdint>
#include <cstddef>

#define NB   16
#define LQS  2048
#define LKS  2048
#define DIN  1024
#define NH   256

// Scratch for projected Q, K, V (fp32). 3 x 33.5 MB, static device arrays (allowed).
__device__ float g_Q[NB * LQS * NH];
__device__ float g_K[NB * LKS * NH];
__device__ float g_V[NB * LKS * NH];

// ---------------------------------------------------------------------------
// Helpers
// ---------------------------------------------------------------------------
__device__ __forceinline__ unsigned f2tf(float x) {
    unsigned r;
    asm("cvt.rna.tf32.f32 %0, %1;" : "=r"(r) : "f"(x));
    return r;
}

__device__ __forceinline__ float tf32r(float x) {
    return __uint_as_float(f2tf(x));
}

// D += A(16x8, row) * B(8x8, col)   tf32 inputs, fp32 accum
__device__ __forceinline__ void mma_tf32(float& d0, float& d1, float& d2, float& d3,
                                         unsigned a0, unsigned a1, unsigned a2, unsigned a3,
                                         unsigned b0, unsigned b1) {
    asm volatile(
        "mma.sync.aligned.m16n8k8.row.col.f32.tf32.tf32.f32 "
        "{%0,%1,%2,%3}, {%4,%5,%6,%7}, {%8,%9}, {%0,%1,%2,%3};\n"
        : "+f"(d0), "+f"(d1), "+f"(d2), "+f"(d3)
        : "r"(a0), "r"(a1), "r"(a2), "r"(a3), "r"(b0), "r"(b1));
}

// ---------------------------------------------------------------------------
// Projection kernel: out[z] = X[z] @ W[z] + b[z]
//   z = 0: g_Q = q_fp @ Wq + bq     (M = NB*LQS)
//   z = 1: g_K = v_ret @ Wk + bk
//   z = 2: g_V = v_ret @ Wv + bv
// CTA tile 128(M) x 128(N), K-step 16. 8 warps, warp tile 32x64.
// ---------------------------------------------------------------------------
#define XS_STRIDE 20    // 16 cols + pad (conflict-free A-frag reads)
#define WS_STRIDE 136   // 128 cols + pad (conflict-free B-frag reads)

__global__ __launch_bounds__(256) void proj_kernel(
    const float* __restrict__ q_fp, const float* __restrict__ v_ret,
    const float* __restrict__ Wq, const float* __restrict__ bq,
    const float* __restrict__ Wk, const float* __restrict__ bk,
    const float* __restrict__ Wv, const float* __restrict__ bv)
{
    __shared__ float Xs[128][XS_STRIDE];
    __shared__ float Ws[16][WS_STRIDE];

    const int z = blockIdx.z;
    const float* X    = (z == 0) ? q_fp : v_ret;
    const float* W    = (z == 0) ? Wq : ((z == 1) ? Wk : Wv);
    const float* bias = (z == 0) ? bq : ((z == 1) ? bk : bv);
    float* out        = (z == 0) ? g_Q : ((z == 1) ? g_K : g_V);

    const int m0 = blockIdx.x * 128;
    const int n0 = blockIdx.y * 128;
    const int tid  = threadIdx.x;
    const int lane = tid & 31;
    const int w    = tid >> 5;
    const int wm   = w & 3;    // 0..3 : 32-row block
    const int wn   = w >> 2;   // 0..1 : 64-col block
    const int g    = lane >> 2;
    const int t4   = lane & 3;

    float acc[2][8][4];
#pragma unroll
    for (int mt = 0; mt < 2; mt++)
#pragma unroll
        for (int nt = 0; nt < 8; nt++)
#pragma unroll
            for (int i = 0; i < 4; i++) acc[mt][nt][i] = 0.0f;

    for (int kt = 0; kt < DIN; kt += 16) {
        // Load X tile 128x16 (512 float4s, 2 per thread), tf32-round at store.
#pragma unroll
        for (int i = 0; i < 2; i++) {
            int idx = tid + i * 256;
            int r = idx >> 2, c4 = idx & 3;
            float4 v = *(const float4*)&X[(size_t)(m0 + r) * DIN + kt + c4 * 4];
            float4 t;
            t.x = tf32r(v.x); t.y = tf32r(v.y); t.z = tf32r(v.z); t.w = tf32r(v.w);
            *(float4*)&Xs[r][c4 * 4] = t;
        }
        // Load W tile 16x128 (512 float4s, 2 per thread)
#pragma unroll
        for (int i = 0; i < 2; i++) {
            int idx = tid + i * 256;
            int r = idx >> 5, c4 = idx & 31;
            float4 v = *(const float4*)&W[(size_t)(kt + r) * NH + n0 + c4 * 4];
            float4 t;
            t.x = tf32r(v.x); t.y = tf32r(v.y); t.z = tf32r(v.z); t.w = tf32r(v.w);
            *(float4*)&Ws[r][c4 * 4] = t;
        }
        __syncthreads();

#pragma unroll
        for (int kc = 0; kc < 16; kc += 8) {
            unsigned a[2][4];
#pragma unroll
            for (int mt = 0; mt < 2; mt++) {
                int r = wm * 32 + mt * 16;
                a[mt][0] = __float_as_uint(Xs[r + g][kc + t4]);
                a[mt][1] = __float_as_uint(Xs[r + 8 + g][kc + t4]);
                a[mt][2] = __float_as_uint(Xs[r + g][kc + t4 + 4]);
                a[mt][3] = __float_as_uint(Xs[r + 8 + g][kc + t4 + 4]);
            }
#pragma unroll
            for (int nt = 0; nt < 8; nt++) {
                int c = wn * 64 + nt * 8 + g;
                unsigned b0 = __float_as_uint(Ws[kc + t4][c]);
                unsigned b1 = __float_as_uint(Ws[kc + t4 + 4][c]);
#pragma unroll
                for (int mt = 0; mt < 2; mt++)
                    mma_tf32(acc[mt][nt][0], acc[mt][nt][1], acc[mt][nt][2], acc[mt][nt][3],
                             a[mt][0], a[mt][1], a[mt][2], a[mt][3], b0, b1);
            }
        }
        __syncthreads();
    }

    // Epilogue: + bias, store fp32 scratch.
#pragma unroll
    for (int mt = 0; mt < 2; mt++) {
#pragma unroll
        for (int nt = 0; nt < 8; nt++) {
            int row = m0 + wm * 32 + mt * 16 + g;
            int col = n0 + wn * 64 + nt * 8 + 2 * t4;
            float b0 = bias[col], b1 = bias[col + 1];
            float2 v0 = make_float2(acc[mt][nt][0] + b0, acc[mt][nt][1] + b1);
            float2 v1 = make_float2(acc[mt][nt][2] + b0, acc[mt][nt][3] + b1);
            *(float2*)&out[(size_t)row * NH + col]       = v0;
            *(float2*)&out[(size_t)(row + 8) * NH + col] = v1;
        }
    }
}

// ---------------------------------------------------------------------------
// Flash attention kernel.
// CTA: batch b, 64 q-rows. 256 threads = 8 warps as 4(m) x 2(n).
// Iterate 32 k-tiles of 64 keys: S = Q K^T / 16 + gamma*log(clip(pi)),
// online softmax (cross-warp stats via smem), O += P @ V.
// ---------------------------------------------------------------------------
#define QK_STRIDE 260   // 256 + 4
#define V_STRIDE  264   // 256 + 8
#define P_STRIDE  68    // 64 + 4

struct SmemAttn {
    float Qs[64][QK_STRIDE];
    float Ks[64][QK_STRIDE];
    float Vs[64][V_STRIDE];
    float Ps[64][P_STRIDE];
    float sMax[2][64];
    float sSum[2][64];
};

extern __shared__ __align__(16) unsigned char smem_raw[];

__global__ __launch_bounds__(256, 1) void attn_kernel(
    const float* __restrict__ pi_star, const float* __restrict__ gamma_p,
    float* __restrict__ out)
{
    SmemAttn& sm = *(SmemAttn*)smem_raw;
    const int b  = blockIdx.y;
    const int q0 = blockIdx.x * 64;
    const int tid  = threadIdx.x;
    const int lane = tid & 31;
    const int w    = tid >> 5;
    const int wm   = w >> 1;   // 0..3 : 16 q-rows
    const int wn   = w & 1;    // 0..1 : 32 keys (S) / 128 H-cols (PV)
    const int g    = lane >> 2;
    const int t4   = lane & 3;
    const float gamma = gamma_p[0];
    const float inv_scale = 1.0f / 16.0f;   // 1/sqrt(H)

    // Load Q tile 64x256 (tf32-rounded)
    {
        const float* Qg = &g_Q[((size_t)b * LQS + q0) * NH];
        for (int i = tid; i < 4096; i += 256) {
            int r = i >> 6, c4 = i & 63;
            float4 v = *(const float4*)&Qg[(size_t)r * NH + c4 * 4];
            float4 t;
            t.x = tf32r(v.x); t.y = tf32r(v.y); t.z = tf32r(v.z); t.w = tf32r(v.w);
            *(float4*)&sm.Qs[r][c4 * 4] = t;
        }
    }

    float o[16][4];
#pragma unroll
    for (int nt = 0; nt < 16; nt++)
#pragma unroll
        for (int i = 0; i < 4; i++) o[nt][i] = 0.0f;

    float mrow0 = -1e30f, mrow1 = -1e30f;
    float lrow0 = 0.0f,  lrow1 = 0.0f;

    const int rloc0 = wm * 16 + g;       // local q row for c0/c1
    const int rloc1 = rloc0 + 8;         // local q row for c2/c3

    for (int kt = 0; kt < LKS / 64; kt++) {
        const int k0 = kt * 64;
        __syncthreads();   // previous PV mma done reading Vs/Ps; stats consumed

        // Load K, V tiles 64x256 (tf32-rounded)
        const float* Kg = &g_K[((size_t)b * LKS + k0) * NH];
        const float* Vg = &g_V[((size_t)b * LKS + k0) * NH];
        for (int i = tid; i < 4096; i += 256) {
            int r = i >> 6, c4 = i & 63;
            float4 kv = *(const float4*)&Kg[(size_t)r * NH + c4 * 4];
            float4 tk;
            tk.x = tf32r(kv.x); tk.y = tf32r(kv.y); tk.z = tf32r(kv.z); tk.w = tf32r(kv.w);
            *(float4*)&sm.Ks[r][c4 * 4] = tk;
            float4 vv = *(const float4*)&Vg[(size_t)r * NH + c4 * 4];
            float4 tv;
            tv.x = tf32r(vv.x); tv.y = tf32r(vv.y); tv.z = tf32r(vv.z); tv.w = tf32r(vv.w);
            *(float4*)&sm.Vs[r][c4 * 4] = tv;
        }
        __syncthreads();

        // S = Q @ K^T  : warp tile 16 rows x 32 keys
        float s[4][4];
#pragma unroll
        for (int nt = 0; nt < 4; nt++)
#pragma unroll
            for (int i = 0; i < 4; i++) s[nt][i] = 0.0f;

#pragma unroll
        for (int kc = 0; kc < 32; kc++) {
            int h = kc * 8;
            int r = wm * 16;
            unsigned a0 = __float_as_uint(sm.Qs[r + g][h + t4]);
            unsigned a1 = __float_as_uint(sm.Qs[r + 8 + g][h + t4]);
            unsigned a2 = __float_as_uint(sm.Qs[r + g][h + t4 + 4]);
            unsigned a3 = __float_as_uint(sm.Qs[r + 8 + g][h + t4 + 4]);
#pragma unroll
            for (int nt = 0; nt < 4; nt++) {
                int key = wn * 32 + nt * 8 + g;
                unsigned b0 = __float_as_uint(sm.Ks[key][h + t4]);
                unsigned b1 = __float_as_uint(sm.Ks[key][h + t4 + 4]);
                mma_tf32(s[nt][0], s[nt][1], s[nt][2], s[nt][3], a0, a1, a2, a3, b0, b1);
            }
        }

        // Add prior-bias mask, track row max.
        float pmax0 = -1e30f, pmax1 = -1e30f;
        const int grow0 = q0 + rloc0;
#pragma unroll
        for (int nt = 0; nt < 4; nt++) {
            int colbase = k0 + wn * 32 + nt * 8 + 2 * t4;
            const float* prow = &pi_star[((size_t)b * LQS + grow0) * LKS + colbase];
            float2 p0 = *(const float2*)prow;                       // row grow0
            float2 p1 = *(const float2*)(prow + (size_t)8 * LKS);   // row grow0+8
            s[nt][0] = s[nt][0] * inv_scale + gamma * __logf(fmaxf(p0.x, 1e-9f));
            s[nt][1] = s[nt][1] * inv_scale + gamma * __logf(fmaxf(p0.y, 1e-9f));
            s[nt][2] = s[nt][2] * inv_scale + gamma * __logf(fmaxf(p1.x, 1e-9f));
            s[nt][3] = s[nt][3] * inv_scale + gamma * __logf(fmaxf(p1.y, 1e-9f));
            pmax0 = fmaxf(pmax0, fmaxf(s[nt][0], s[nt][1]));
            pmax1 = fmaxf(pmax1, fmaxf(s[nt][2], s[nt][3]));
        }
        pmax0 = fmaxf(pmax0, __shfl_xor_sync(0xffffffffu, pmax0, 1));
        pmax0 = fmaxf(pmax0, __shfl_xor_sync(0xffffffffu, pmax0, 2));
        pmax1 = fmaxf(pmax1, __shfl_xor_sync(0xffffffffu, pmax1, 1));
        pmax1 = fmaxf(pmax1, __shfl_xor_sync(0xffffffffu, pmax1, 2));
        if (t4 == 0) {
            sm.sMax[wn][rloc0] = pmax0;
            sm.sMax[wn][rloc1] = pmax1;
        }
        __syncthreads();

        float mnew0 = fmaxf(mrow0, fmaxf(sm.sMax[0][rloc0], sm.sMax[1][rloc0]));
        float mnew1 = fmaxf(mrow1, fmaxf(sm.sMax[0][rloc1], sm.sMax[1][rloc1]));
        float alpha0 = __expf(mrow0 - mnew0);
        float alpha1 = __expf(mrow1 - mnew1);
        mrow0 = mnew0;
        mrow1 = mnew1;

        // P = exp(S - m_new); partial row sums; stage P (tf32) to smem.
        float psum0 = 0.0f, psum1 = 0.0f;
#pragma unroll
        for (int nt = 0; nt < 4; nt++) {
            float p00 = __expf(s[nt][0] - mnew0);
            float p01 = __expf(s[nt][1] - mnew0);
            float p10 = __expf(s[nt][2] - mnew1);
            float p11 = __expf(s[nt][3] - mnew1);
            psum0 += p00 + p01;
            psum1 += p10 + p11;
            int pc = wn * 32 + nt * 8 + 2 * t4;
            *(float2*)&sm.Ps[rloc0][pc] = make_float2(tf32r(p00), tf32r(p01));
            *(float2*)&sm.Ps[rloc1][pc] = make_float2(tf32r(p10), tf32r(p11));
        }
        psum0 += __shfl_xor_sync(0xffffffffu, psum0, 1);
        psum0 += __shfl_xor_sync(0xffffffffu, psum0, 2);
        psum1 += __shfl_xor_sync(0xffffffffu, psum1, 1);
        psum1 += __shfl_xor_sync(0xffffffffu, psum1, 2);
        if (t4 == 0) {
            sm.sSum[wn][rloc0] = psum0;
            sm.sSum[wn][rloc1] = psum1;
        }

        // Rescale accumulators by alpha (rows match c0/c1 -> alpha0, c2/c3 -> alpha1).
#pragma unroll
        for (int nt = 0; nt < 16; nt++) {
            o[nt][0] *= alpha0; o[nt][1] *= alpha0;
            o[nt][2] *= alpha1; o[nt][3] *= alpha1;
        }
        __syncthreads();   // Ps + sSum visible

        lrow0 = lrow0 * alpha0 + sm.sSum[0][rloc0] + sm.sSum[1][rloc0];
        lrow1 = lrow1 * alpha1 + sm.sSum[0][rloc1] + sm.sSum[1][rloc1];

        // O += P @ V : warp tile 16 rows x 128 H-cols
#pragma unroll
        for (int kc = 0; kc < 8; kc++) {
            int kk = kc * 8;
            int r = wm * 16;
            unsigned a0 = __float_as_uint(sm.Ps[r + g][kk + t4]);
            unsigned a1 = __float_as_uint(sm.Ps[r + 8 + g][kk + t4]);
            unsigned a2 = __float_as_uint(sm.Ps[r + g][kk + t4 + 4]);
            unsigned a3 = __float_as_uint(sm.Ps[r + 8 + g][kk + t4 + 4]);
#pragma unroll
            for (int nt = 0; nt < 16; nt++) {
                int hc = wn * 128 + nt * 8 + g;
                unsigned b0 = __float_as_uint(sm.Vs[kk + t4][hc]);
                unsigned b1 = __float_as_uint(sm.Vs[kk + t4 + 4][hc]);
                mma_tf32(o[nt][0], o[nt][1], o[nt][2], o[nt][3], a0, a1, a2, a3, b0, b1);
            }
        }
    }

    // Final: O /= l, write out.
    float il0 = 1.0f / lrow0;
    float il1 = 1.0f / lrow1;
    const int grow0 = q0 + rloc0;
#pragma unroll
    for (int nt = 0; nt < 16; nt++) {
        int col = wn * 128 + nt * 8 + 2 * t4;
        float* orow0 = &out[((size_t)b * LQS + grow0) * NH + col];
        float* orow1 = &out[((size_t)b * LQS + grow0 + 8) * NH + col];
        *(float2*)orow0 = make_float2(o[nt][0] * il0, o[nt][1] * il0);
        *(float2*)orow1 = make_float2(o[nt][2] * il1, o[nt][3] * il1);
    }
}

// ---------------------------------------------------------------------------
// Launch
// ---------------------------------------------------------------------------
extern "C" void kernel_launch(void* const* d_in, const int* in_sizes, int n_in,
                              void* d_out, int out_size)
{
    const float* q_fp  = (const float*)d_in[0];
    const float* v_ret = (const float*)d_in[1];
    const float* pi    = (const float*)d_in[2];
    const float* Wq    = (const float*)d_in[3];
    const float* bq    = (const float*)d_in[4];
    const float* Wk    = (const float*)d_in[5];
    const float* bk    = (const float*)d_in[6];
    const float* Wv    = (const float*)d_in[7];
    const float* bv    = (const float*)d_in[8];
    const float* gamma = (const float*)d_in[9];
    float* out = (float*)d_out;

    (void)in_sizes; (void)n_in; (void)out_size;

    // Projections: M = NB*LQS = 32768 rows for all three outputs.
    dim3 gproj((NB * LQS) / 128, NH / 128, 3);
    proj_kernel<<<gproj, 256>>>(q_fp, v_ret, Wq, bq, Wk, bk, Wv, bv);

    // Attention
    cudaFuncSetAttribute(attn_kernel, cudaFuncAttributeMaxDynamicSharedMemorySize,
                         (int)sizeof(SmemAttn));
    dim3 gattn(LQS / 64, NB);
    attn_kernel<<<gattn, 256, sizeof(SmemAttn)>>>(pi, gamma, out);
}

// round 3
// speedup vs baseline: 1.0033x; 1.0033x over previous
#include <cuda_runtime.h>
#include <cstdint>
#include <cstddef>

#define NB   16
#define LQS  2048
#define LKS  2048
#define DIN  1024
#define NH   256

// Scratch for projected Q, K, V (fp32). 3 x 33.5 MB, static device arrays (allowed).
__device__ float g_Q[NB * LQS * NH];
__device__ float g_K[NB * LKS * NH];
__device__ float g_V[NB * LKS * NH];

// ---------------------------------------------------------------------------
// Helpers
// ---------------------------------------------------------------------------
__device__ __forceinline__ unsigned f2tf(float x) {
    unsigned r;
    asm("cvt.rna.tf32.f32 %0, %1;" : "=r"(r) : "f"(x));
    return r;
}

__device__ __forceinline__ float tf32r(float x) {
    return __uint_as_float(f2tf(x));
}

// D += A(16x8, row) * B(8x8, col)   tf32 inputs, fp32 accum
__device__ __forceinline__ void mma_tf32(float& d0, float& d1, float& d2, float& d3,
                                         unsigned a0, unsigned a1, unsigned a2, unsigned a3,
                                         unsigned b0, unsigned b1) {
    asm volatile(
        "mma.sync.aligned.m16n8k8.row.col.f32.tf32.tf32.f32 "
        "{%0,%1,%2,%3}, {%4,%5,%6,%7}, {%8,%9}, {%0,%1,%2,%3};\n"
        : "+f"(d0), "+f"(d1), "+f"(d2), "+f"(d3)
        : "r"(a0), "r"(a1), "r"(a2), "r"(a3), "r"(b0), "r"(b1));
}

// ---------------------------------------------------------------------------
// Projection kernel: out[z] = X[z] @ W[z] + b[z]
//   z = 0: g_Q = q_fp @ Wq + bq     (M = NB*LQS)
//   z = 1: g_K = v_ret @ Wk + bk
//   z = 2: g_V = v_ret @ Wv + bv
// CTA tile 128(M) x 128(N), K-step 16. 8 warps, warp tile 32x64.
// ---------------------------------------------------------------------------
#define XS_STRIDE 20    // 16 cols + pad (conflict-free A-frag reads)
#define WS_STRIDE 136   // 128 cols + pad (conflict-free B-frag reads)

__global__ __launch_bounds__(256) void proj_kernel(
    const float* __restrict__ q_fp, const float* __restrict__ v_ret,
    const float* __restrict__ Wq, const float* __restrict__ bq,
    const float* __restrict__ Wk, const float* __restrict__ bk,
    const float* __restrict__ Wv, const float* __restrict__ bv)
{
    __shared__ float Xs[128][XS_STRIDE];
    __shared__ float Ws[16][WS_STRIDE];

    const int z = blockIdx.z;
    const float* X    = (z == 0) ? q_fp : v_ret;
    const float* W    = (z == 0) ? Wq : ((z == 1) ? Wk : Wv);
    const float* bias = (z == 0) ? bq : ((z == 1) ? bk : bv);
    float* out        = (z == 0) ? g_Q : ((z == 1) ? g_K : g_V);

    const int m0 = blockIdx.x * 128;
    const int n0 = blockIdx.y * 128;
    const int tid  = threadIdx.x;
    const int lane = tid & 31;
    const int w    = tid >> 5;
    const int wm   = w & 3;    // 0..3 : 32-row block
    const int wn   = w >> 2;   // 0..1 : 64-col block
    const int g    = lane >> 2;
    const int t4   = lane & 3;

    float acc[2][8][4];
#pragma unroll
    for (int mt = 0; mt < 2; mt++)
#pragma unroll
        for (int nt = 0; nt < 8; nt++)
#pragma unroll
            for (int i = 0; i < 4; i++) acc[mt][nt][i] = 0.0f;

    for (int kt = 0; kt < DIN; kt += 16) {
        // Load X tile 128x16 (512 float4s, 2 per thread), tf32-round at store.
#pragma unroll
        for (int i = 0; i < 2; i++) {
            int idx = tid + i * 256;
            int r = idx >> 2, c4 = idx & 3;
            float4 v = *(const float4*)&X[(size_t)(m0 + r) * DIN + kt + c4 * 4];
            float4 t;
            t.x = tf32r(v.x); t.y = tf32r(v.y); t.z = tf32r(v.z); t.w = tf32r(v.w);
            *(float4*)&Xs[r][c4 * 4] = t;
        }
        // Load W tile 16x128 (512 float4s, 2 per thread)
#pragma unroll
        for (int i = 0; i < 2; i++) {
            int idx = tid + i * 256;
            int r = idx >> 5, c4 = idx & 31;
            float4 v = *(const float4*)&W[(size_t)(kt + r) * NH + n0 + c4 * 4];
            float4 t;
            t.x = tf32r(v.x); t.y = tf32r(v.y); t.z = tf32r(v.z); t.w = tf32r(v.w);
            *(float4*)&Ws[r][c4 * 4] = t;
        }
        __syncthreads();

#pragma unroll
        for (int kc = 0; kc < 16; kc += 8) {
            unsigned a[2][4];
#pragma unroll
            for (int mt = 0; mt < 2; mt++) {
                int r = wm * 32 + mt * 16;
                a[mt][0] = __float_as_uint(Xs[r + g][kc + t4]);
                a[mt][1] = __float_as_uint(Xs[r + 8 + g][kc + t4]);
                a[mt][2] = __float_as_uint(Xs[r + g][kc + t4 + 4]);
                a[mt][3] = __float_as_uint(Xs[r + 8 + g][kc + t4 + 4]);
            }
#pragma unroll
            for (int nt = 0; nt < 8; nt++) {
                int c = wn * 64 + nt * 8 + g;
                unsigned b0 = __float_as_uint(Ws[kc + t4][c]);
                unsigned b1 = __float_as_uint(Ws[kc + t4 + 4][c]);
#pragma unroll
                for (int mt = 0; mt < 2; mt++)
                    mma_tf32(acc[mt][nt][0], acc[mt][nt][1], acc[mt][nt][2], acc[mt][nt][3],
                             a[mt][0], a[mt][1], a[mt][2], a[mt][3], b0, b1);
            }
        }
        __syncthreads();
    }

    // Epilogue: + bias, store fp32 scratch.
#pragma unroll
    for (int mt = 0; mt < 2; mt++) {
#pragma unroll
        for (int nt = 0; nt < 8; nt++) {
            int row = m0 + wm * 32 + mt * 16 + g;
            int col = n0 + wn * 64 + nt * 8 + 2 * t4;
            float b0 = bias[col], b1 = bias[col + 1];
            float2 v0 = make_float2(acc[mt][nt][0] + b0, acc[mt][nt][1] + b1);
            float2 v1 = make_float2(acc[mt][nt][2] + b0, acc[mt][nt][3] + b1);
            *(float2*)&out[(size_t)row * NH + col]       = v0;
            *(float2*)&out[(size_t)(row + 8) * NH + col] = v1;
        }
    }
}

// ---------------------------------------------------------------------------
// Flash attention kernel.
// CTA: batch b, 64 q-rows. 256 threads = 8 warps as 4(m) x 2(n).
// Iterate 32 k-tiles of 64 keys: S = Q K^T / 16 + gamma*log(clip(pi)),
// online softmax (cross-warp stats via smem), O += P @ V.
// ---------------------------------------------------------------------------
#define QK_STRIDE 260   // 256 + 4
#define V_STRIDE  264   // 256 + 8
#define P_STRIDE  68    // 64 + 4

struct SmemAttn {
    float Qs[64][QK_STRIDE];
    float Ks[64][QK_STRIDE];
    float Vs[64][V_STRIDE];
    float Ps[64][P_STRIDE];
    float sMax[2][64];
    float sSum[2][64];
};

extern __shared__ __align__(16) unsigned char smem_raw[];

__global__ __launch_bounds__(256, 1) void attn_kernel(
    const float* __restrict__ pi_star, const float* __restrict__ gamma_p,
    float* __restrict__ out)
{
    SmemAttn& sm = *(SmemAttn*)smem_raw;
    const int b  = blockIdx.y;
    const int q0 = blockIdx.x * 64;
    const int tid  = threadIdx.x;
    const int lane = tid & 31;
    const int w    = tid >> 5;
    const int wm   = w >> 1;   // 0..3 : 16 q-rows
    const int wn   = w & 1;    // 0..1 : 32 keys (S) / 128 H-cols (PV)
    const int g    = lane >> 2;
    const int t4   = lane & 3;
    const float gamma = gamma_p[0];
    const float inv_scale = 1.0f / 16.0f;   // 1/sqrt(H)

    // Load Q tile 64x256 (tf32-rounded)
    {
        const float* Qg = &g_Q[((size_t)b * LQS + q0) * NH];
        for (int i = tid; i < 4096; i += 256) {
            int r = i >> 6, c4 = i & 63;
            float4 v = *(const float4*)&Qg[(size_t)r * NH + c4 * 4];
            float4 t;
            t.x = tf32r(v.x); t.y = tf32r(v.y); t.z = tf32r(v.z); t.w = tf32r(v.w);
            *(float4*)&sm.Qs[r][c4 * 4] = t;
        }
    }

    float o[16][4];
#pragma unroll
    for (int nt = 0; nt < 16; nt++)
#pragma unroll
        for (int i = 0; i < 4; i++) o[nt][i] = 0.0f;

    float mrow0 = -1e30f, mrow1 = -1e30f;
    float lrow0 = 0.0f,  lrow1 = 0.0f;

    const int rloc0 = wm * 16 + g;       // local q row for c0/c1
    const int rloc1 = rloc0 + 8;         // local q row for c2/c3

    for (int kt = 0; kt < LKS / 64; kt++) {
        const int k0 = kt * 64;
        __syncthreads();   // previous PV mma done reading Vs/Ps; stats consumed

        // Load K, V tiles 64x256 (tf32-rounded)
        const float* Kg = &g_K[((size_t)b * LKS + k0) * NH];
        const float* Vg = &g_V[((size_t)b * LKS + k0) * NH];
        for (int i = tid; i < 4096; i += 256) {
            int r = i >> 6, c4 = i & 63;
            float4 kv = *(const float4*)&Kg[(size_t)r * NH + c4 * 4];
            float4 tk;
            tk.x = tf32r(kv.x); tk.y = tf32r(kv.y); tk.z = tf32r(kv.z); tk.w = tf32r(kv.w);
            *(float4*)&sm.Ks[r][c4 * 4] = tk;
            float4 vv = *(const float4*)&Vg[(size_t)r * NH + c4 * 4];
            float4 tv;
            tv.x = tf32r(vv.x); tv.y = tf32r(vv.y); tv.z = tf32r(vv.z); tv.w = tf32r(vv.w);
            *(float4*)&sm.Vs[r][c4 * 4] = tv;
        }
        __syncthreads();

        // S = Q @ K^T  : warp tile 16 rows x 32 keys
        float s[4][4];
#pragma unroll
        for (int nt = 0; nt < 4; nt++)
#pragma unroll
            for (int i = 0; i < 4; i++) s[nt][i] = 0.0f;

#pragma unroll
        for (int kc = 0; kc < 32; kc++) {
            int h = kc * 8;
            int r = wm * 16;
            unsigned a0 = __float_as_uint(sm.Qs[r + g][h + t4]);
            unsigned a1 = __float_as_uint(sm.Qs[r + 8 + g][h + t4]);
            unsigned a2 = __float_as_uint(sm.Qs[r + g][h + t4 + 4]);
            unsigned a3 = __float_as_uint(sm.Qs[r + 8 + g][h + t4 + 4]);
#pragma unroll
            for (int nt = 0; nt < 4; nt++) {
                int key = wn * 32 + nt * 8 + g;
                unsigned b0 = __float_as_uint(sm.Ks[key][h + t4]);
                unsigned b1 = __float_as_uint(sm.Ks[key][h + t4 + 4]);
                mma_tf32(s[nt][0], s[nt][1], s[nt][2], s[nt][3], a0, a1, a2, a3, b0, b1);
            }
        }

        // Add prior-bias mask, track row max.
        float pmax0 = -1e30f, pmax1 = -1e30f;
        const int grow0 = q0 + rloc0;
#pragma unroll
        for (int nt = 0; nt < 4; nt++) {
            int colbase = k0 + wn * 32 + nt * 8 + 2 * t4;
            const float* prow = &pi_star[((size_t)b * LQS + grow0) * LKS + colbase];
            float2 p0 = *(const float2*)prow;                       // row grow0
            float2 p1 = *(const float2*)(prow + (size_t)8 * LKS);   // row grow0+8
            s[nt][0] = s[nt][0] * inv_scale + gamma * __logf(fmaxf(p0.x, 1e-9f));
            s[nt][1] = s[nt][1] * inv_scale + gamma * __logf(fmaxf(p0.y, 1e-9f));
            s[nt][2] = s[nt][2] * inv_scale + gamma * __logf(fmaxf(p1.x, 1e-9f));
            s[nt][3] = s[nt][3] * inv_scale + gamma * __logf(fmaxf(p1.y, 1e-9f));
            pmax0 = fmaxf(pmax0, fmaxf(s[nt][0], s[nt][1]));
            pmax1 = fmaxf(pmax1, fmaxf(s[nt][2], s[nt][3]));
        }
        pmax0 = fmaxf(pmax0, __shfl_xor_sync(0xffffffffu, pmax0, 1));
        pmax0 = fmaxf(pmax0, __shfl_xor_sync(0xffffffffu, pmax0, 2));
        pmax1 = fmaxf(pmax1, __shfl_xor_sync(0xffffffffu, pmax1, 1));
        pmax1 = fmaxf(pmax1, __shfl_xor_sync(0xffffffffu, pmax1, 2));
        if (t4 == 0) {
            sm.sMax[wn][rloc0] = pmax0;
            sm.sMax[wn][rloc1] = pmax1;
        }
        __syncthreads();

        float mnew0 = fmaxf(mrow0, fmaxf(sm.sMax[0][rloc0], sm.sMax[1][rloc0]));
        float mnew1 = fmaxf(mrow1, fmaxf(sm.sMax[0][rloc1], sm.sMax[1][rloc1]));
        float alpha0 = __expf(mrow0 - mnew0);
        float alpha1 = __expf(mrow1 - mnew1);
        mrow0 = mnew0;
        mrow1 = mnew1;

        // P = exp(S - m_new); partial row sums; stage P (tf32) to smem.
        float psum0 = 0.0f, psum1 = 0.0f;
#pragma unroll
        for (int nt = 0; nt < 4; nt++) {
            float p00 = __expf(s[nt][0] - mnew0);
            float p01 = __expf(s[nt][1] - mnew0);
            float p10 = __expf(s[nt][2] - mnew1);
            float p11 = __expf(s[nt][3] - mnew1);
            psum0 += p00 + p01;
            psum1 += p10 + p11;
            int pc = wn * 32 + nt * 8 + 2 * t4;
            *(float2*)&sm.Ps[rloc0][pc] = make_float2(tf32r(p00), tf32r(p01));
            *(float2*)&sm.Ps[rloc1][pc] = make_float2(tf32r(p10), tf32r(p11));
        }
        psum0 += __shfl_xor_sync(0xffffffffu, psum0, 1);
        psum0 += __shfl_xor_sync(0xffffffffu, psum0, 2);
        psum1 += __shfl_xor_sync(0xffffffffu, psum1, 1);
        psum1 += __shfl_xor_sync(0xffffffffu, psum1, 2);
        if (t4 == 0) {
            sm.sSum[wn][rloc0] = psum0;
            sm.sSum[wn][rloc1] = psum1;
        }

        // Rescale accumulators by alpha (rows match c0/c1 -> alpha0, c2/c3 -> alpha1).
#pragma unroll
        for (int nt = 0; nt < 16; nt++) {
            o[nt][0] *= alpha0; o[nt][1] *= alpha0;
            o[nt][2] *= alpha1; o[nt][3] *= alpha1;
        }
        __syncthreads();   // Ps + sSum visible

        lrow0 = lrow0 * alpha0 + sm.sSum[0][rloc0] + sm.sSum[1][rloc0];
        lrow1 = lrow1 * alpha1 + sm.sSum[0][rloc1] + sm.sSum[1][rloc1];

        // O += P @ V : warp tile 16 rows x 128 H-cols
#pragma unroll
        for (int kc = 0; kc < 8; kc++) {
            int kk = kc * 8;
            int r = wm * 16;
            unsigned a0 = __float_as_uint(sm.Ps[r + g][kk + t4]);
            unsigned a1 = __float_as_uint(sm.Ps[r + 8 + g][kk + t4]);
            unsigned a2 = __float_as_uint(sm.Ps[r + g][kk + t4 + 4]);
            unsigned a3 = __float_as_uint(sm.Ps[r + 8 + g][kk + t4 + 4]);
#pragma unroll
            for (int nt = 0; nt < 16; nt++) {
                int hc = wn * 128 + nt * 8 + g;
                unsigned b0 = __float_as_uint(sm.Vs[kk + t4][hc]);
                unsigned b1 = __float_as_uint(sm.Vs[kk + t4 + 4][hc]);
                mma_tf32(o[nt][0], o[nt][1], o[nt][2], o[nt][3], a0, a1, a2, a3, b0, b1);
            }
        }
    }

    // Final: O /= l, write out.
    float il0 = 1.0f / lrow0;
    float il1 = 1.0f / lrow1;
    const int grow0 = q0 + rloc0;
#pragma unroll
    for (int nt = 0; nt < 16; nt++) {
        int col = wn * 128 + nt * 8 + 2 * t4;
        float* orow0 = &out[((size_t)b * LQS + grow0) * NH + col];
        float* orow1 = &out[((size_t)b * LQS + grow0 + 8) * NH + col];
        *(float2*)orow0 = make_float2(o[nt][0] * il0, o[nt][1] * il0);
        *(float2*)orow1 = make_float2(o[nt][2] * il1, o[nt][3] * il1);
    }
}

// ---------------------------------------------------------------------------
// Launch
// ---------------------------------------------------------------------------
extern "C" void kernel_launch(void* const* d_in, const int* in_sizes, int n_in,
                              void* d_out, int out_size)
{
    const float* q_fp  = (const float*)d_in[0];
    const float* v_ret = (const float*)d_in[1];
    const float* pi    = (const float*)d_in[2];
    const float* Wq    = (const float*)d_in[3];
    const float* bq    = (const float*)d_in[4];
    const float* Wk    = (const float*)d_in[5];
    const float* bk    = (const float*)d_in[6];
    const float* Wv    = (const float*)d_in[7];
    const float* bv    = (const float*)d_in[8];
    const float* gamma = (const float*)d_in[9];
    float* out = (float*)d_out;

    (void)in_sizes; (void)n_in; (void)out_size;

    // Projections: M = NB*LQS = 32768 rows for all three outputs.
    dim3 gproj((NB * LQS) / 128, NH / 128, 3);
    proj_kernel<<<gproj, 256>>>(q_fp, v_ret, Wq, bq, Wk, bk, Wv, bv);

    // Attention
    cudaFuncSetAttribute(attn_kernel, cudaFuncAttributeMaxDynamicSharedMemorySize,
                         (int)sizeof(SmemAttn));
    dim3 gattn(LQS / 64, NB);
    attn_kernel<<<gattn, 256, sizeof(SmemAttn)>>>(pi, gamma, out);
}